// round 15
// baseline (speedup 1.0000x reference)
#include <cuda_runtime.h>
#include <cstdint>
#include <cstddef>

#define B_ 4
#define N_ 1024
#define C_ 768
#define H_ 12
#define D_ 64
#define SCALE_ 0.125f   // 64^-0.5

// ---------------- scratch (device globals; no cudaMalloc allowed) ----------
__device__ float g_q[(size_t)B_ * H_ * N_ * D_];   // 12.6 MB
__device__ float g_k[(size_t)B_ * H_ * N_ * D_];
__device__ float g_v[(size_t)B_ * H_ * N_ * D_];
__device__ float g_s[(size_t)B_ * H_ * N_ * N_];   // 192 MB (scores, reused in-place for probs)
__device__ float g_o[(size_t)B_ * N_ * C_];        // 12.6 MB (attn out, pre-proj)

// ============================================================================
// Kernel 1: QKV GEMM.  y[row][col] = sum_k x[row][k] * w_qkv[col][k]
// row in [0,4096), col in [0,2304). Scatter into g_q/g_k/g_v [B,H,N,D].
// 64x64 tile, BK=16, 16x16 threads, 4x4 micro-tile (interleaved mapping).
// ============================================================================
__global__ __launch_bounds__(256) void qkv_gemm_kernel(
    const float* __restrict__ x, const float* __restrict__ w)
{
    __shared__ float As[16][65];   // As[k][i]
    __shared__ float Bs[16][65];   // Bs[k][j]
    const int tx = threadIdx.x, ty = threadIdx.y;
    const int tid = ty * 16 + tx;
    const int row0 = blockIdx.y * 64;
    const int col0 = blockIdx.x * 64;

    float acc[4][4] = {};

    const int li = tid >> 2;      // 0..63 : tile row/col for loads
    const int lk = tid & 3;       // 0..3  : float4 index along k

    for (int k0 = 0; k0 < C_; k0 += 16) {
        float4 va = *(const float4*)(x + (size_t)(row0 + li) * C_ + k0 + lk * 4);
        As[lk * 4 + 0][li] = va.x; As[lk * 4 + 1][li] = va.y;
        As[lk * 4 + 2][li] = va.z; As[lk * 4 + 3][li] = va.w;
        float4 vb = *(const float4*)(w + (size_t)(col0 + li) * C_ + k0 + lk * 4);
        Bs[lk * 4 + 0][li] = vb.x; Bs[lk * 4 + 1][li] = vb.y;
        Bs[lk * 4 + 2][li] = vb.z; Bs[lk * 4 + 3][li] = vb.w;
        __syncthreads();

        #pragma unroll
        for (int kk = 0; kk < 16; ++kk) {
            float a[4], b[4];
            #pragma unroll
            for (int i = 0; i < 4; ++i) a[i] = As[kk][ty + 16 * i];
            #pragma unroll
            for (int j = 0; j < 4; ++j) b[j] = Bs[kk][tx + 16 * j];
            #pragma unroll
            for (int i = 0; i < 4; ++i)
                #pragma unroll
                for (int j = 0; j < 4; ++j)
                    acc[i][j] += a[i] * b[j];
        }
        __syncthreads();
    }

    #pragma unroll
    for (int i = 0; i < 4; ++i) {
        int row = row0 + ty + 16 * i;
        int b = row >> 10;
        int n = row & (N_ - 1);
        #pragma unroll
        for (int j = 0; j < 4; ++j) {
            int col = col0 + tx + 16 * j;
            int which = col / C_;
            int c = col - which * C_;
            int h = c >> 6;
            int d = c & 63;
            float* dst = (which == 0) ? g_q : (which == 1) ? g_k : g_v;
            dst[(((size_t)b * H_ + h) * N_ + n) * D_ + d] = acc[i][j];
        }
    }
}

// ============================================================================
// Kernel 2: S[b,h,n,m] = SCALE * dot(Q[b,h,n,:], K[b,h,m,:]) + mask[b,n,m]
// Batched 1024x1024x64 GEMM per (b,h). Tile 64(n) x 64(m), full K=64 in smem.
// ============================================================================
__global__ __launch_bounds__(256) void qk_kernel(const float* __restrict__ mask)
{
    const int bh = blockIdx.z;
    const int b  = bh / H_;
    const float* Q = g_q + (size_t)bh * N_ * D_;
    const float* K = g_k + (size_t)bh * N_ * D_;
    float* S = g_s + (size_t)bh * N_ * N_;

    const int n0 = blockIdx.y * 64;
    const int m0 = blockIdx.x * 64;
    const int tx = threadIdx.x, ty = threadIdx.y;
    const int tid = ty * 16 + tx;

    __shared__ float Qs[D_][65];   // Qs[d][n]
    __shared__ float Ks[D_][65];   // Ks[d][m]

    // load 64 rows x 64 d each (1024 float4 total across both, 4 iters)
    for (int e = tid; e < 64 * 16; e += 256) {
        int r  = e >> 4;          // row within tile
        int c4 = e & 15;          // float4 along d
        float4 vq = *(const float4*)(Q + (size_t)(n0 + r) * D_ + c4 * 4);
        Qs[c4 * 4 + 0][r] = vq.x; Qs[c4 * 4 + 1][r] = vq.y;
        Qs[c4 * 4 + 2][r] = vq.z; Qs[c4 * 4 + 3][r] = vq.w;
        float4 vk = *(const float4*)(K + (size_t)(m0 + r) * D_ + c4 * 4);
        Ks[c4 * 4 + 0][r] = vk.x; Ks[c4 * 4 + 1][r] = vk.y;
        Ks[c4 * 4 + 2][r] = vk.z; Ks[c4 * 4 + 3][r] = vk.w;
    }
    __syncthreads();

    float acc[4][4] = {};
    #pragma unroll 8
    for (int d = 0; d < D_; ++d) {
        float qr[4], kr[4];
        #pragma unroll
        for (int i = 0; i < 4; ++i) qr[i] = Qs[d][ty + 16 * i];
        #pragma unroll
        for (int j = 0; j < 4; ++j) kr[j] = Ks[d][tx + 16 * j];
        #pragma unroll
        for (int i = 0; i < 4; ++i)
            #pragma unroll
            for (int j = 0; j < 4; ++j)
                acc[i][j] += qr[i] * kr[j];
    }

    #pragma unroll
    for (int i = 0; i < 4; ++i) {
        int n = n0 + ty + 16 * i;
        const float* mrow = mask + ((size_t)b * N_ + n) * N_;
        #pragma unroll
        for (int j = 0; j < 4; ++j) {
            int m = m0 + tx + 16 * j;
            S[(size_t)n * N_ + m] = acc[i][j] * SCALE_ + mrow[m];
        }
    }
}

// ============================================================================
// Kernel 3: fused talking-heads pre-mix -> softmax -> post-mix, in place on g_s.
// One block per (b,n). Each of 256 threads owns 4 columns m (strided), holding
// all 12 heads of those columns in registers (48 regs). Block reductions give
// per-head max/sum. Memory: read 192MB + write 192MB.
// ============================================================================
__global__ __launch_bounds__(256) void mix_softmax_kernel(
    const float* __restrict__ wpre, const float* __restrict__ wpost)
{
    __shared__ float wpre_s[H_ * H_];
    __shared__ float wpost_s[H_ * H_];
    __shared__ float red[8 * H_];
    __shared__ float rowmax[H_];
    __shared__ float rowinv[H_];

    const int n = blockIdx.x;
    const int b = blockIdx.y;
    const int tid = threadIdx.x;

    if (tid < H_ * H_) { wpre_s[tid] = wpre[tid]; wpost_s[tid] = wpost[tid]; }

    const size_t base = (size_t)b * H_ * N_ * N_ + (size_t)n * N_;
    const size_t hstr = (size_t)N_ * N_;

    float col[4][H_];
    #pragma unroll
    for (int q = 0; q < 4; ++q) {
        int m = tid + 256 * q;
        #pragma unroll
        for (int h = 0; h < H_; ++h)
            col[q][h] = g_s[base + (size_t)h * hstr + m];
    }
    __syncthreads();   // weights visible

    // pre-softmax head mixing (per column, in registers)
    #pragma unroll
    for (int q = 0; q < 4; ++q) {
        float t[H_];
        #pragma unroll
        for (int g = 0; g < H_; ++g) {
            float s = 0.f;
            #pragma unroll
            for (int h = 0; h < H_; ++h) s += wpre_s[g * H_ + h] * col[q][h];
            t[g] = s;
        }
        #pragma unroll
        for (int g = 0; g < H_; ++g) col[q][g] = t[g];
    }

    // per-head max
    float lmax[H_];
    #pragma unroll
    for (int h = 0; h < H_; ++h) lmax[h] = -1e30f;
    #pragma unroll
    for (int q = 0; q < 4; ++q)
        #pragma unroll
        for (int h = 0; h < H_; ++h) lmax[h] = fmaxf(lmax[h], col[q][h]);
    #pragma unroll
    for (int h = 0; h < H_; ++h)
        for (int o = 16; o; o >>= 1)
            lmax[h] = fmaxf(lmax[h], __shfl_xor_sync(0xffffffffu, lmax[h], o));
    const int warp = tid >> 5, lane = tid & 31;
    if (lane == 0) {
        #pragma unroll
        for (int h = 0; h < H_; ++h) red[warp * H_ + h] = lmax[h];
    }
    __syncthreads();
    if (tid < H_) {
        float mx = red[tid];
        #pragma unroll
        for (int w = 1; w < 8; ++w) mx = fmaxf(mx, red[w * H_ + tid]);
        rowmax[tid] = mx;
    }
    __syncthreads();

    // exp + per-head sum
    float lsum[H_];
    #pragma unroll
    for (int h = 0; h < H_; ++h) lsum[h] = 0.f;
    #pragma unroll
    for (int q = 0; q < 4; ++q)
        #pragma unroll
        for (int h = 0; h < H_; ++h) {
            float e = __expf(col[q][h] - rowmax[h]);
            col[q][h] = e;
            lsum[h] += e;
        }
    #pragma unroll
    for (int h = 0; h < H_; ++h)
        for (int o = 16; o; o >>= 1)
            lsum[h] += __shfl_xor_sync(0xffffffffu, lsum[h], o);
    if (lane == 0) {
        #pragma unroll
        for (int h = 0; h < H_; ++h) red[warp * H_ + h] = lsum[h];
    }
    __syncthreads();
    if (tid < H_) {
        float s = 0.f;
        #pragma unroll
        for (int w = 0; w < 8; ++w) s += red[w * H_ + tid];
        rowinv[tid] = 1.0f / s;
    }
    __syncthreads();

    // post-softmax mixing + write back in place
    #pragma unroll
    for (int q = 0; q < 4; ++q) {
        int m = tid + 256 * q;
        float p[H_];
        #pragma unroll
        for (int h = 0; h < H_; ++h) p[h] = col[q][h] * rowinv[h];
        #pragma unroll
        for (int g = 0; g < H_; ++g) {
            float s = 0.f;
            #pragma unroll
            for (int h = 0; h < H_; ++h) s += wpost_s[g * H_ + h] * p[h];
            g_s[base + (size_t)g * hstr + m] = s;
        }
    }
}

// ============================================================================
// Kernel 4: O[b,g,n,d] = sum_m P[b,g,n,m] * V[b,g,m,d].
// Batched 1024x64x1024 GEMM per (b,g). Tile 64(n) x 64(d), BK=32.
// Writes directly into [B,N,C] layout.
// ============================================================================
__global__ __launch_bounds__(256) void av_kernel()
{
    const int bh = blockIdx.z;
    const int b = bh / H_;
    const int g = bh % H_;
    const float* P = g_s + (size_t)bh * N_ * N_;
    const float* V = g_v + (size_t)bh * N_ * D_;
    const int n0 = blockIdx.x * 64;
    const int tx = threadIdx.x, ty = threadIdx.y;
    const int tid = ty * 16 + tx;

    __shared__ float Ps[32][65];   // Ps[mk][n]
    __shared__ float Vs[32][65];   // Vs[mk][d]

    float acc[4][4] = {};

    for (int m0 = 0; m0 < N_; m0 += 32) {
        // P tile: 64 n x 32 m  -> 512 float4, 2 per thread
        for (int e = tid; e < 512; e += 256) {
            int r  = e >> 3;      // n within tile
            int c4 = e & 7;       // float4 along m
            float4 v = *(const float4*)(P + (size_t)(n0 + r) * N_ + m0 + c4 * 4);
            Ps[c4 * 4 + 0][r] = v.x; Ps[c4 * 4 + 1][r] = v.y;
            Ps[c4 * 4 + 2][r] = v.z; Ps[c4 * 4 + 3][r] = v.w;
        }
        // V tile: 32 m x 64 d -> 512 float4
        for (int e = tid; e < 512; e += 256) {
            int r  = e >> 4;      // m within tile
            int c4 = e & 15;      // float4 along d
            float4 v = *(const float4*)(V + (size_t)(m0 + r) * D_ + c4 * 4);
            Vs[r][c4 * 4 + 0] = v.x; Vs[r][c4 * 4 + 1] = v.y;
            Vs[r][c4 * 4 + 2] = v.z; Vs[r][c4 * 4 + 3] = v.w;
        }
        __syncthreads();

        #pragma unroll 8
        for (int mk = 0; mk < 32; ++mk) {
            float pr[4], vr[4];
            #pragma unroll
            for (int i = 0; i < 4; ++i) pr[i] = Ps[mk][ty + 16 * i];
            #pragma unroll
            for (int j = 0; j < 4; ++j) vr[j] = Vs[mk][tx + 16 * j];
            #pragma unroll
            for (int i = 0; i < 4; ++i)
                #pragma unroll
                for (int j = 0; j < 4; ++j)
                    acc[i][j] += pr[i] * vr[j];
        }
        __syncthreads();
    }

    #pragma unroll
    for (int i = 0; i < 4; ++i) {
        int n = n0 + ty + 16 * i;
        #pragma unroll
        for (int j = 0; j < 4; ++j) {
            int d = tx + 16 * j;
            g_o[((size_t)b * N_ + n) * C_ + g * D_ + d] = acc[i][j];
        }
    }
}

// ============================================================================
// Kernel 5: out = O @ w_proj^T + b_proj.  [4096x768] @ [768x768]^T.
// ============================================================================
__global__ __launch_bounds__(256) void proj_kernel(
    const float* __restrict__ w, const float* __restrict__ bias,
    float* __restrict__ out)
{
    __shared__ float As[16][65];
    __shared__ float Bs[16][65];
    const int tx = threadIdx.x, ty = threadIdx.y;
    const int tid = ty * 16 + tx;
    const int row0 = blockIdx.y * 64;
    const int col0 = blockIdx.x * 64;

    float acc[4][4] = {};
    const int li = tid >> 2;
    const int lk = tid & 3;

    for (int k0 = 0; k0 < C_; k0 += 16) {
        float4 va = *(const float4*)(g_o + (size_t)(row0 + li) * C_ + k0 + lk * 4);
        As[lk * 4 + 0][li] = va.x; As[lk * 4 + 1][li] = va.y;
        As[lk * 4 + 2][li] = va.z; As[lk * 4 + 3][li] = va.w;
        float4 vb = *(const float4*)(w + (size_t)(col0 + li) * C_ + k0 + lk * 4);
        Bs[lk * 4 + 0][li] = vb.x; Bs[lk * 4 + 1][li] = vb.y;
        Bs[lk * 4 + 2][li] = vb.z; Bs[lk * 4 + 3][li] = vb.w;
        __syncthreads();

        #pragma unroll
        for (int kk = 0; kk < 16; ++kk) {
            float a[4], b[4];
            #pragma unroll
            for (int i = 0; i < 4; ++i) a[i] = As[kk][ty + 16 * i];
            #pragma unroll
            for (int j = 0; j < 4; ++j) b[j] = Bs[kk][tx + 16 * j];
            #pragma unroll
            for (int i = 0; i < 4; ++i)
                #pragma unroll
                for (int j = 0; j < 4; ++j)
                    acc[i][j] += a[i] * b[j];
        }
        __syncthreads();
    }

    #pragma unroll
    for (int i = 0; i < 4; ++i) {
        int row = row0 + ty + 16 * i;
        #pragma unroll
        for (int j = 0; j < 4; ++j) {
            int col = col0 + tx + 16 * j;
            out[(size_t)row * C_ + col] = acc[i][j] + bias[col];
        }
    }
}

// ============================================================================
extern "C" void kernel_launch(void* const* d_in, const int* in_sizes, int n_in,
                              void* d_out, int out_size)
{
    const float* x     = (const float*)d_in[0];   // [4,1024,768]
    const float* mask  = (const float*)d_in[1];   // [4,1024,1024]
    const float* wqkv  = (const float*)d_in[2];   // [2304,768]
    const float* wproj = (const float*)d_in[3];   // [768,768]
    const float* bproj = (const float*)d_in[4];   // [768]
    const float* wpre  = (const float*)d_in[5];   // [12,12]
    const float* wpost = (const float*)d_in[6];   // [12,12]
    float* out = (float*)d_out;                   // [4,1024,768]

    dim3 t2(16, 16);

    // 1) QKV projection + scatter to [B,H,N,D]
    qkv_gemm_kernel<<<dim3((3 * C_) / 64, (B_ * N_) / 64), t2>>>(x, wqkv);

    // 2) scores = scale * Q K^T + mask  (48 batched GEMMs)
    qk_kernel<<<dim3(N_ / 64, N_ / 64, B_ * H_), t2>>>(mask);

    // 3) fused pre-mix / softmax / post-mix (in place on g_s)
    mix_softmax_kernel<<<dim3(N_, B_), 256>>>(wpre, wpost);

    // 4) O = P @ V  (48 batched GEMMs), written as [B,N,C]
    av_kernel<<<dim3(N_ / 64, 1, B_ * H_), t2>>>();

    // 5) final projection + bias
    proj_kernel<<<dim3(C_ / 64, (B_ * N_) / 64), t2>>>(wproj, bproj, out);
}

// round 16
// speedup vs baseline: 1.0007x; 1.0007x over previous
#include <cuda_runtime.h>
#include <cstdint>
#include <cstddef>

#define B_ 4
#define N_ 1024
#define C_ 768
#define H_ 12
#define D_ 64
#define SCALE_ 0.125f   // 64^-0.5

// ---------------- scratch (device globals; no cudaMalloc allowed) ----------
__device__ float g_q[(size_t)B_ * H_ * N_ * D_];   // 12.6 MB
__device__ float g_k[(size_t)B_ * H_ * N_ * D_];
__device__ float g_v[(size_t)B_ * H_ * N_ * D_];
__device__ float g_s[(size_t)B_ * H_ * N_ * N_];   // 192 MB (scores, reused in-place for probs)
__device__ float g_o[(size_t)B_ * N_ * C_];        // 12.6 MB (attn out, pre-proj)

// ============================================================================
// Kernel 1: QKV GEMM.  y[row][col] = sum_k x[row][k] * w_qkv[col][k]
// row in [0,4096), col in [0,2304). Scatter into g_q/g_k/g_v [B,H,N,D].
// 64x64 tile, BK=16, 16x16 threads, 4x4 micro-tile (interleaved mapping).
// ============================================================================
__global__ __launch_bounds__(256) void qkv_gemm_kernel(
    const float* __restrict__ x, const float* __restrict__ w)
{
    __shared__ float As[16][65];   // As[k][i]
    __shared__ float Bs[16][65];   // Bs[k][j]
    const int tx = threadIdx.x, ty = threadIdx.y;
    const int tid = ty * 16 + tx;
    const int row0 = blockIdx.y * 64;
    const int col0 = blockIdx.x * 64;

    float acc[4][4] = {};

    const int li = tid >> 2;      // 0..63 : tile row/col for loads
    const int lk = tid & 3;       // 0..3  : float4 index along k

    for (int k0 = 0; k0 < C_; k0 += 16) {
        float4 va = *(const float4*)(x + (size_t)(row0 + li) * C_ + k0 + lk * 4);
        As[lk * 4 + 0][li] = va.x; As[lk * 4 + 1][li] = va.y;
        As[lk * 4 + 2][li] = va.z; As[lk * 4 + 3][li] = va.w;
        float4 vb = *(const float4*)(w + (size_t)(col0 + li) * C_ + k0 + lk * 4);
        Bs[lk * 4 + 0][li] = vb.x; Bs[lk * 4 + 1][li] = vb.y;
        Bs[lk * 4 + 2][li] = vb.z; Bs[lk * 4 + 3][li] = vb.w;
        __syncthreads();

        #pragma unroll
        for (int kk = 0; kk < 16; ++kk) {
            float a[4], b[4];
            #pragma unroll
            for (int i = 0; i < 4; ++i) a[i] = As[kk][ty + 16 * i];
            #pragma unroll
            for (int j = 0; j < 4; ++j) b[j] = Bs[kk][tx + 16 * j];
            #pragma unroll
            for (int i = 0; i < 4; ++i)
                #pragma unroll
                for (int j = 0; j < 4; ++j)
                    acc[i][j] += a[i] * b[j];
        }
        __syncthreads();
    }

    #pragma unroll
    for (int i = 0; i < 4; ++i) {
        int row = row0 + ty + 16 * i;
        int b = row >> 10;
        int n = row & (N_ - 1);
        #pragma unroll
        for (int j = 0; j < 4; ++j) {
            int col = col0 + tx + 16 * j;
            int which = col / C_;
            int c = col - which * C_;
            int h = c >> 6;
            int d = c & 63;
            float* dst = (which == 0) ? g_q : (which == 1) ? g_k : g_v;
            dst[(((size_t)b * H_ + h) * N_ + n) * D_ + d] = acc[i][j];
        }
    }
}

// ============================================================================
// Kernel 2: S[b,h,n,m] = SCALE * dot(Q[b,h,n,:], K[b,h,m,:]) + mask[b,n,m]
// Batched 1024x1024x64 GEMM per (b,h). Tile 64(n) x 64(m), full K=64 in smem.
// ============================================================================
__global__ __launch_bounds__(256) void qk_kernel(const float* __restrict__ mask)
{
    const int bh = blockIdx.z;
    const int b  = bh / H_;
    const float* Q = g_q + (size_t)bh * N_ * D_;
    const float* K = g_k + (size_t)bh * N_ * D_;
    float* S = g_s + (size_t)bh * N_ * N_;

    const int n0 = blockIdx.y * 64;
    const int m0 = blockIdx.x * 64;
    const int tx = threadIdx.x, ty = threadIdx.y;
    const int tid = ty * 16 + tx;

    __shared__ float Qs[D_][65];   // Qs[d][n]
    __shared__ float Ks[D_][65];   // Ks[d][m]

    // load 64 rows x 64 d each (1024 float4 total across both, 4 iters)
    for (int e = tid; e < 64 * 16; e += 256) {
        int r  = e >> 4;          // row within tile
        int c4 = e & 15;          // float4 along d
        float4 vq = *(const float4*)(Q + (size_t)(n0 + r) * D_ + c4 * 4);
        Qs[c4 * 4 + 0][r] = vq.x; Qs[c4 * 4 + 1][r] = vq.y;
        Qs[c4 * 4 + 2][r] = vq.z; Qs[c4 * 4 + 3][r] = vq.w;
        float4 vk = *(const float4*)(K + (size_t)(m0 + r) * D_ + c4 * 4);
        Ks[c4 * 4 + 0][r] = vk.x; Ks[c4 * 4 + 1][r] = vk.y;
        Ks[c4 * 4 + 2][r] = vk.z; Ks[c4 * 4 + 3][r] = vk.w;
    }
    __syncthreads();

    float acc[4][4] = {};
    #pragma unroll 8
    for (int d = 0; d < D_; ++d) {
        float qr[4], kr[4];
        #pragma unroll
        for (int i = 0; i < 4; ++i) qr[i] = Qs[d][ty + 16 * i];
        #pragma unroll
        for (int j = 0; j < 4; ++j) kr[j] = Ks[d][tx + 16 * j];
        #pragma unroll
        for (int i = 0; i < 4; ++i)
            #pragma unroll
            for (int j = 0; j < 4; ++j)
                acc[i][j] += qr[i] * kr[j];
    }

    #pragma unroll
    for (int i = 0; i < 4; ++i) {
        int n = n0 + ty + 16 * i;
        const float* mrow = mask + ((size_t)b * N_ + n) * N_;
        #pragma unroll
        for (int j = 0; j < 4; ++j) {
            int m = m0 + tx + 16 * j;
            S[(size_t)n * N_ + m] = acc[i][j] * SCALE_ + mrow[m];
        }
    }
}

// ============================================================================
// Kernel 3: fused talking-heads pre-mix -> softmax -> post-mix, in place on g_s.
// One block per (b,n). Each of 256 threads owns 4 columns m (strided), holding
// all 12 heads of those columns in registers (48 regs). Block reductions give
// per-head max/sum. Memory: read 192MB + write 192MB.
// ============================================================================
__global__ __launch_bounds__(256) void mix_softmax_kernel(
    const float* __restrict__ wpre, const float* __restrict__ wpost)
{
    __shared__ float wpre_s[H_ * H_];
    __shared__ float wpost_s[H_ * H_];
    __shared__ float red[8 * H_];
    __shared__ float rowmax[H_];
    __shared__ float rowinv[H_];

    const int n = blockIdx.x;
    const int b = blockIdx.y;
    const int tid = threadIdx.x;

    if (tid < H_ * H_) { wpre_s[tid] = wpre[tid]; wpost_s[tid] = wpost[tid]; }

    const size_t base = (size_t)b * H_ * N_ * N_ + (size_t)n * N_;
    const size_t hstr = (size_t)N_ * N_;

    float col[4][H_];
    #pragma unroll
    for (int q = 0; q < 4; ++q) {
        int m = tid + 256 * q;
        #pragma unroll
        for (int h = 0; h < H_; ++h)
            col[q][h] = g_s[base + (size_t)h * hstr + m];
    }
    __syncthreads();   // weights visible

    // pre-softmax head mixing (per column, in registers)
    #pragma unroll
    for (int q = 0; q < 4; ++q) {
        float t[H_];
        #pragma unroll
        for (int g = 0; g < H_; ++g) {
            float s = 0.f;
            #pragma unroll
            for (int h = 0; h < H_; ++h) s += wpre_s[g * H_ + h] * col[q][h];
            t[g] = s;
        }
        #pragma unroll
        for (int g = 0; g < H_; ++g) col[q][g] = t[g];
    }

    // per-head max
    float lmax[H_];
    #pragma unroll
    for (int h = 0; h < H_; ++h) lmax[h] = -1e30f;
    #pragma unroll
    for (int q = 0; q < 4; ++q)
        #pragma unroll
        for (int h = 0; h < H_; ++h) lmax[h] = fmaxf(lmax[h], col[q][h]);
    #pragma unroll
    for (int h = 0; h < H_; ++h)
        for (int o = 16; o; o >>= 1)
            lmax[h] = fmaxf(lmax[h], __shfl_xor_sync(0xffffffffu, lmax[h], o));
    const int warp = tid >> 5, lane = tid & 31;
    if (lane == 0) {
        #pragma unroll
        for (int h = 0; h < H_; ++h) red[warp * H_ + h] = lmax[h];
    }
    __syncthreads();
    if (tid < H_) {
        float mx = red[tid];
        #pragma unroll
        for (int w = 1; w < 8; ++w) mx = fmaxf(mx, red[w * H_ + tid]);
        rowmax[tid] = mx;
    }
    __syncthreads();

    // exp + per-head sum
    float lsum[H_];
    #pragma unroll
    for (int h = 0; h < H_; ++h) lsum[h] = 0.f;
    #pragma unroll
    for (int q = 0; q < 4; ++q)
        #pragma unroll
        for (int h = 0; h < H_; ++h) {
            float e = __expf(col[q][h] - rowmax[h]);
            col[q][h] = e;
            lsum[h] += e;
        }
    #pragma unroll
    for (int h = 0; h < H_; ++h)
        for (int o = 16; o; o >>= 1)
            lsum[h] += __shfl_xor_sync(0xffffffffu, lsum[h], o);
    if (lane == 0) {
        #pragma unroll
        for (int h = 0; h < H_; ++h) red[warp * H_ + h] = lsum[h];
    }
    __syncthreads();
    if (tid < H_) {
        float s = 0.f;
        #pragma unroll
        for (int w = 0; w < 8; ++w) s += red[w * H_ + tid];
        rowinv[tid] = 1.0f / s;
    }
    __syncthreads();

    // post-softmax mixing + write back in place
    #pragma unroll
    for (int q = 0; q < 4; ++q) {
        int m = tid + 256 * q;
        float p[H_];
        #pragma unroll
        for (int h = 0; h < H_; ++h) p[h] = col[q][h] * rowinv[h];
        #pragma unroll
        for (int g = 0; g < H_; ++g) {
            float s = 0.f;
            #pragma unroll
            for (int h = 0; h < H_; ++h) s += wpost_s[g * H_ + h] * p[h];
            g_s[base + (size_t)g * hstr + m] = s;
        }
    }
}

// ============================================================================
// Kernel 4: O[b,g,n,d] = sum_m P[b,g,n,m] * V[b,g,m,d].
// Batched 1024x64x1024 GEMM per (b,g). Tile 64(n) x 64(d), BK=32.
// Writes directly into [B,N,C] layout.
// ============================================================================
__global__ __launch_bounds__(256) void av_kernel()
{
    const int bh = blockIdx.z;
    const int b = bh / H_;
    const int g = bh % H_;
    const float* P = g_s + (size_t)bh * N_ * N_;
    const float* V = g_v + (size_t)bh * N_ * D_;
    const int n0 = blockIdx.x * 64;
    const int tx = threadIdx.x, ty = threadIdx.y;
    const int tid = ty * 16 + tx;

    __shared__ float Ps[32][65];   // Ps[mk][n]
    __shared__ float Vs[32][65];   // Vs[mk][d]

    float acc[4][4] = {};

    for (int m0 = 0; m0 < N_; m0 += 32) {
        // P tile: 64 n x 32 m  -> 512 float4, 2 per thread
        for (int e = tid; e < 512; e += 256) {
            int r  = e >> 3;      // n within tile
            int c4 = e & 7;       // float4 along m
            float4 v = *(const float4*)(P + (size_t)(n0 + r) * N_ + m0 + c4 * 4);
            Ps[c4 * 4 + 0][r] = v.x; Ps[c4 * 4 + 1][r] = v.y;
            Ps[c4 * 4 + 2][r] = v.z; Ps[c4 * 4 + 3][r] = v.w;
        }
        // V tile: 32 m x 64 d -> 512 float4
        for (int e = tid; e < 512; e += 256) {
            int r  = e >> 4;      // m within tile
            int c4 = e & 15;      // float4 along d
            float4 v = *(const float4*)(V + (size_t)(m0 + r) * D_ + c4 * 4);
            Vs[r][c4 * 4 + 0] = v.x; Vs[r][c4 * 4 + 1] = v.y;
            Vs[r][c4 * 4 + 2] = v.z; Vs[r][c4 * 4 + 3] = v.w;
        }
        __syncthreads();

        #pragma unroll 8
        for (int mk = 0; mk < 32; ++mk) {
            float pr[4], vr[4];
            #pragma unroll
            for (int i = 0; i < 4; ++i) pr[i] = Ps[mk][ty + 16 * i];
            #pragma unroll
            for (int j = 0; j < 4; ++j) vr[j] = Vs[mk][tx + 16 * j];
            #pragma unroll
            for (int i = 0; i < 4; ++i)
                #pragma unroll
                for (int j = 0; j < 4; ++j)
                    acc[i][j] += pr[i] * vr[j];
        }
        __syncthreads();
    }

    #pragma unroll
    for (int i = 0; i < 4; ++i) {
        int n = n0 + ty + 16 * i;
        #pragma unroll
        for (int j = 0; j < 4; ++j) {
            int d = tx + 16 * j;
            g_o[((size_t)b * N_ + n) * C_ + g * D_ + d] = acc[i][j];
        }
    }
}

// ============================================================================
// Kernel 5: out = O @ w_proj^T + b_proj.  [4096x768] @ [768x768]^T.
// ============================================================================
__global__ __launch_bounds__(256) void proj_kernel(
    const float* __restrict__ w, const float* __restrict__ bias,
    float* __restrict__ out)
{
    __shared__ float As[16][65];
    __shared__ float Bs[16][65];
    const int tx = threadIdx.x, ty = threadIdx.y;
    const int tid = ty * 16 + tx;
    const int row0 = blockIdx.y * 64;
    const int col0 = blockIdx.x * 64;

    float acc[4][4] = {};
    const int li = tid >> 2;
    const int lk = tid & 3;

    for (int k0 = 0; k0 < C_; k0 += 16) {
        float4 va = *(const float4*)(g_o + (size_t)(row0 + li) * C_ + k0 + lk * 4);
        As[lk * 4 + 0][li] = va.x; As[lk * 4 + 1][li] = va.y;
        As[lk * 4 + 2][li] = va.z; As[lk * 4 + 3][li] = va.w;
        float4 vb = *(const float4*)(w + (size_t)(col0 + li) * C_ + k0 + lk * 4);
        Bs[lk * 4 + 0][li] = vb.x; Bs[lk * 4 + 1][li] = vb.y;
        Bs[lk * 4 + 2][li] = vb.z; Bs[lk * 4 + 3][li] = vb.w;
        __syncthreads();

        #pragma unroll
        for (int kk = 0; kk < 16; ++kk) {
            float a[4], b[4];
            #pragma unroll
            for (int i = 0; i < 4; ++i) a[i] = As[kk][ty + 16 * i];
            #pragma unroll
            for (int j = 0; j < 4; ++j) b[j] = Bs[kk][tx + 16 * j];
            #pragma unroll
            for (int i = 0; i < 4; ++i)
                #pragma unroll
                for (int j = 0; j < 4; ++j)
                    acc[i][j] += a[i] * b[j];
        }
        __syncthreads();
    }

    #pragma unroll
    for (int i = 0; i < 4; ++i) {
        int row = row0 + ty + 16 * i;
        #pragma unroll
        for (int j = 0; j < 4; ++j) {
            int col = col0 + tx + 16 * j;
            out[(size_t)row * C_ + col] = acc[i][j] + bias[col];
        }
    }
}

// ============================================================================
extern "C" void kernel_launch(void* const* d_in, const int* in_sizes, int n_in,
                              void* d_out, int out_size)
{
    const float* x     = (const float*)d_in[0];   // [4,1024,768]
    const float* mask  = (const float*)d_in[1];   // [4,1024,1024]
    const float* wqkv  = (const float*)d_in[2];   // [2304,768]
    const float* wproj = (const float*)d_in[3];   // [768,768]
    const float* bproj = (const float*)d_in[4];   // [768]
    const float* wpre  = (const float*)d_in[5];   // [12,12]
    const float* wpost = (const float*)d_in[6];   // [12,12]
    float* out = (float*)d_out;                   // [4,1024,768]

    dim3 t2(16, 16);

    // 1) QKV projection + scatter to [B,H,N,D]
    qkv_gemm_kernel<<<dim3((3 * C_) / 64, (B_ * N_) / 64), t2>>>(x, wqkv);

    // 2) scores = scale * Q K^T + mask  (48 batched GEMMs)
    qk_kernel<<<dim3(N_ / 64, N_ / 64, B_ * H_), t2>>>(mask);

    // 3) fused pre-mix / softmax / post-mix (in place on g_s)
    mix_softmax_kernel<<<dim3(N_, B_), 256>>>(wpre, wpost);

    // 4) O = P @ V  (48 batched GEMMs), written as [B,N,C]
    av_kernel<<<dim3(N_ / 64, 1, B_ * H_), t2>>>();

    // 5) final projection + bias
    proj_kernel<<<dim3(C_ / 64, (B_ * N_) / 64), t2>>>(wproj, bproj, out);
}